// round 12
// baseline (speedup 1.0000x reference)
#include <cuda_runtime.h>
#include <math_constants.h>

#define B    32
#define T    336
#define C    7
#define NSH  5
#define NG   4
#define NF   140            // 4 groups * 5 * 7
#define OUTC 10
#define NWORKBLK (B * C * NSH)      // 1120 worker blocks (bc, nn)
#define NHEAD    21                 // 20 dot blocks + 1 loss block

// offsets in d_out (floats): out[320] | dists[4480] | probs[4480] | loss[1]
#define OFF_OUT   0
#define OFF_DIST  320
#define OFF_PROB  (320 + B*NF)
#define OFF_LOSS  (320 + 2*B*NF)

#define SXN 352            // padded row length (floats, zero tail)

__device__ int g_ctr  = 0;   // worker blocks completed
__device__ int g_ctr2 = 0;   // head blocks completed

// ---------------------------------------------------------------------------
// Run M contiguous passes (p0 .. p0+M-1) of the L-sweep. Pass p covers window
// pairs with base beta = ll + 32p (clamped; duplicates are min-safe).
// float2 rolling body: per h per m: 1 LDS.64 + 8 FADD; w broadcast LDS.64.
// Warp-reduces its partial min and atomicMin's it into smin[gslot].
// ---------------------------------------------------------------------------
template<int L, int M>
__device__ __forceinline__ void run_pass(const float* __restrict__ sx,
                                         const float* __restrict__ swg,
                                         int ll, int p0,
                                         unsigned* __restrict__ sminp) {
    constexpr int TW      = T - L + 1;
    constexpr int BETAMAX = (TW - 1) / 2;
    constexpr int H       = L / 2;

    const float2* sx2 = reinterpret_cast<const float2*>(sx);
    const float2* sw2 = reinterpret_cast<const float2*>(swg);

    int    beta[M];
    float  a0[M], a1[M];
    float2 cur[M];
    #pragma unroll
    for (int m = 0; m < M; m++) {
        int bt = ll + 32 * (p0 + m);
        if (bt > BETAMAX) bt = BETAMAX;            // duplicate work, min-safe
        beta[m] = bt;
        a0[m] = 0.f;
        a1[m] = (2 * bt + 1 < TW) ? 0.f : CUDART_INF_F;
        cur[m] = sx2[bt];
    }

    #pragma unroll 2
    for (int h = 0; h < H; h++) {
        const float2 w = sw2[h];                    // broadcast LDS.64
        #pragma unroll
        for (int m = 0; m < M; m++) {
            const float2 nxt = sx2[beta[m] + h + 1]; // stride-1 lanes, no conflict
            a0[m] += fabsf(cur[m].x - w.x);
            a1[m] += fabsf(cur[m].y - w.x);
            a0[m] += fabsf(cur[m].y - w.y);
            a1[m] += fabsf(nxt.x    - w.y);
            cur[m] = nxt;
        }
    }
    if (L & 1) {                                    // final step l = L-1
        const float w = swg[L - 1];
        #pragma unroll
        for (int m = 0; m < M; m++) {
            a0[m] += fabsf(cur[m].x - w);
            a1[m] += fabsf(cur[m].y - w);
        }
    }

    float mn = CUDART_INF_F;
    #pragma unroll
    for (int m = 0; m < M; m++) mn = fminf(mn, fminf(a0[m], a1[m]));
    #pragma unroll
    for (int o = 16; o > 0; o >>= 1)
        mn = fminf(mn, __shfl_xor_sync(0xffffffffu, mn, o));
    if (ll == 0) atomicMin(sminp, __float_as_uint(mn));   // d>=0: bits monotone
}

// sw row offsets (even): g0@0(34) g1@36(68) g2@104(101) g3@208(168)
#define SW_TOT 376

__constant__ float c_invL[4] = { 1.f/34.f, 1.f/68.f, 1.f/101.f, 1.f/168.f };

// ---------------------------------------------------------------------------
// Single launch. grid.x = 1120 workers + 21 head blocks, 128 threads.
// Worker block = one (bc, nn); warps run a BALANCED mix of (g, pass) items:
//   w0: g3 p0-1        + g0 p0          (370 units)
//   w1: g3 p2 + g1 p0-1 + g0 p1-2       (372)
//   w2: g2 p0-2 + g1 p2                 (371)
//   w3: g2 p3 + g1 p3-4 + g0 p3-4       (305)
// ---------------------------------------------------------------------------
__global__ __launch_bounds__(128, 8) void fused_kernel(
        const float* __restrict__ x,
        const float* __restrict__ w0,
        const float* __restrict__ w1,
        const float* __restrict__ w2,
        const float* __restrict__ w3,
        const float* __restrict__ Wout,
        float* __restrict__ d_out) {
    const int bid = blockIdx.x;
    const int tid = threadIdx.x;          // 128

    if (bid < NWORKBLK) {
        // ================= WORKER =================
        const int nn = bid % NSH;
        const int bc = bid / NSH;
        const int b  = bc / C;
        const int ch = bc % C;
        const int wp = tid >> 5;             // warp 0..3
        const int ll = tid & 31;

        __shared__ __align__(16) float sx[SXN];
        __shared__ __align__(16) float sw[SW_TOT];
        __shared__ float red[8];
        __shared__ unsigned smin[4];

        // ---- normalization: one pass sum + sumsq over the (b,ch) row ----
        const float* xrow = x + (size_t)b * T * C + ch;   // stride C over t
        float vals[3];
        float s = 0.f, ss = 0.f;
        #pragma unroll
        for (int i = 0; i < 3; i++) {
            int t = tid + i * 128;
            float v = (t < T) ? xrow[(size_t)t * C] : 0.f;
            vals[i] = v;
            s += v;
            ss += v * v;
        }
        #pragma unroll
        for (int o = 16; o > 0; o >>= 1) {
            s  += __shfl_xor_sync(0xffffffffu, s, o);
            ss += __shfl_xor_sync(0xffffffffu, ss, o);
        }
        if (ll == 0) { red[wp] = s; red[4 + wp] = ss; }
        if (tid < 4) smin[tid] = 0x7f800000u;   // +inf bits

        // ---- warp wp loads shapelet row of group wp (all 4 rows needed) ----
        {
            int L, goff;
            const float* wg;
            switch (wp) {
                case 0:  L = 34;  goff = 0;   wg = w0; break;
                case 1:  L = 68;  goff = 36;  wg = w1; break;
                case 2:  L = 101; goff = 104; wg = w2; break;
                default: L = 168; goff = 208; wg = w3; break;
            }
            const float* wrow = wg + (size_t)(nn * C + ch) * L;
            for (int i = ll; i < L; i += 32) sw[goff + i] = wrow[i];
        }

        __syncthreads();
        const float stot  = red[0] + red[1] + red[2] + red[3];
        const float sstot = red[4] + red[5] + red[6] + red[7];
        const float mu  = stot * (1.0f / (float)T);
        const float var = (sstot - (float)T * mu * mu) * (1.0f / (float)(T - 1));
        const float inv = 1.0f / (sqrtf(fmaxf(var, 0.f)) + 1e-8f);

        #pragma unroll
        for (int i = 0; i < 3; i++) {
            int t = tid + i * 128;
            if (t < T) sx[t] = (vals[i] - mu) * inv;
        }
        if (tid < SXN - T) sx[T + tid] = 0.f;   // zero pad (only +inf pairs read)
        __syncthreads();

        // ---- balanced (g, pass) execution ----
        switch (wp) {
            case 0:
                run_pass<168, 2>(sx, sw + 208, ll, 0, &smin[3]);
                run_pass<34,  1>(sx, sw + 0,   ll, 0, &smin[0]);
                break;
            case 1:
                run_pass<168, 1>(sx, sw + 208, ll, 2, &smin[3]);
                run_pass<68,  2>(sx, sw + 36,  ll, 0, &smin[1]);
                run_pass<34,  2>(sx, sw + 0,   ll, 1, &smin[0]);
                break;
            case 2:
                run_pass<101, 3>(sx, sw + 104, ll, 0, &smin[2]);
                run_pass<68,  1>(sx, sw + 36,  ll, 2, &smin[1]);
                break;
            default:
                run_pass<101, 1>(sx, sw + 104, ll, 3, &smin[2]);
                run_pass<68,  2>(sx, sw + 36,  ll, 3, &smin[1]);
                run_pass<34,  2>(sx, sw + 0,   ll, 3, &smin[0]);
                break;
        }
        __syncthreads();

        if (tid < 4) {                      // one thread per g writes results
            const float dmin = __uint_as_float(smin[tid]) * c_invL[tid];
            const int idx = b * NF + tid * (NSH * C) + nn * C + ch;
            d_out[OFF_DIST + idx] = dmin;
            d_out[OFF_PROB + idx] = expf(-dmin * dmin);   // EPS_GATE = 1
        }
        __syncthreads();
        if (tid == 0) {
            __threadfence();
            atomicAdd(&g_ctr, 1);           // publish this block's 4 results
        }
    } else {
        // ================= HEAD =================
        const int h = bid - NWORKBLK;    // 0..20

        if (tid == 0) {
            while (atomicAdd(&g_ctr, 0) < NWORKBLK) __nanosleep(64);
        }
        __syncthreads();
        __threadfence();                  // acquire published probs

        if (h < 20) {
            // 16 dots per block; warp wp does 4 dots
            const int wp = tid >> 5;
            const int ln = tid & 31;
            const float* probs = d_out + OFF_PROB;
            #pragma unroll
            for (int d = 0; d < 4; d++) {
                const int dot = h * 16 + wp * 4 + d;     // < 320
                const int bb = dot / OUTC;
                const int o  = dot % OUTC;
                const float* p  = probs + bb * NF;
                const float* wv = Wout + o * NF;
                float v = 0.f;
                #pragma unroll
                for (int f = ln; f < NF; f += 32) v += p[f] * wv[f];
                #pragma unroll
                for (int off = 16; off > 0; off >>= 1)
                    v += __shfl_xor_sync(0xffffffffu, v, off);
                if (ln == 0) d_out[OFF_OUT + dot] = v;
            }
        } else {
            // loss = 0.1 * mean|Wout|
            __shared__ float sred[4];
            float v = 0.f;
            #pragma unroll
            for (int i = tid; i < OUTC * NF; i += 128) v += fabsf(Wout[i]);
            #pragma unroll
            for (int off = 16; off > 0; off >>= 1)
                v += __shfl_xor_sync(0xffffffffu, v, off);
            if ((tid & 31) == 0) sred[tid >> 5] = v;
            __syncthreads();
            if (tid == 0) {
                float tot = sred[0] + sred[1] + sred[2] + sred[3];
                d_out[OFF_LOSS] = 0.1f * tot / (float)(OUTC * NF);
            }
        }

        __syncthreads();
        if (tid == 0) {
            int v = atomicAdd(&g_ctr2, 1);
            if (v == NHEAD - 1) {
                // last head block resets counters for the next graph replay
                atomicExch(&g_ctr, 0);
                atomicExch(&g_ctr2, 0);
            }
        }
    }
}

// ---------------------------------------------------------------------------
extern "C" void kernel_launch(void* const* d_in, const int* in_sizes, int n_in,
                              void* d_out, int out_size) {
    const float* x    = (const float*)d_in[0];
    const float* w0   = (const float*)d_in[1];
    const float* w1   = (const float*)d_in[2];
    const float* w2   = (const float*)d_in[3];
    const float* w3   = (const float*)d_in[4];
    const float* Wout = (const float*)d_in[5];
    float* out = (float*)d_out;

    fused_kernel<<<NWORKBLK + NHEAD, 128>>>(x, w0, w1, w2, w3, Wout, out);
}

// round 13
// speedup vs baseline: 1.0091x; 1.0091x over previous
#include <cuda_runtime.h>
#include <math_constants.h>

#define B    32
#define T    336
#define C    7
#define NSH  5
#define NG   4
#define NF   140            // 4 groups * 5 * 7
#define OUTC 10
#define NWORKBLK (B * C * NSH)      // 1120 worker blocks (bc, nn), 8 warps each
#define NHEAD    21                 // 20 dot blocks + 1 loss block

// offsets in d_out (floats): out[320] | dists[4480] | probs[4480] | loss[1]
#define OFF_OUT   0
#define OFF_DIST  320
#define OFF_PROB  (320 + B*NF)
#define OFF_LOSS  (320 + 2*B*NF)

#define SXN 352            // padded row length (floats, zero tail)

__device__ int g_ctr  = 0;   // worker blocks completed
__device__ int g_ctr2 = 0;   // head blocks completed

// ---------------------------------------------------------------------------
// Run M contiguous passes (p0 .. p0+M-1) of the L-sweep. Pass p covers window
// pairs with base beta = ll + 32p (clamped; duplicates are min-safe).
// float2 rolling body: per h per m: 1 LDS.64 + 8 FADD; w broadcast LDS.64.
// Warp-reduces its partial min and atomicMin's it into smin[gslot].
// ---------------------------------------------------------------------------
template<int L, int M>
__device__ __forceinline__ void run_pass(const float* __restrict__ sx,
                                         const float* __restrict__ swg,
                                         int ll, int p0,
                                         unsigned* __restrict__ sminp) {
    constexpr int TW      = T - L + 1;
    constexpr int BETAMAX = (TW - 1) / 2;
    constexpr int H       = L / 2;

    const float2* sx2 = reinterpret_cast<const float2*>(sx);
    const float2* sw2 = reinterpret_cast<const float2*>(swg);

    int    beta[M];
    float  a0[M], a1[M];
    float2 cur[M];
    #pragma unroll
    for (int m = 0; m < M; m++) {
        int bt = ll + 32 * (p0 + m);
        if (bt > BETAMAX) bt = BETAMAX;            // duplicate work, min-safe
        beta[m] = bt;
        a0[m] = 0.f;
        a1[m] = (2 * bt + 1 < TW) ? 0.f : CUDART_INF_F;
        cur[m] = sx2[bt];
    }

    #pragma unroll 2
    for (int h = 0; h < H; h++) {
        const float2 w = sw2[h];                    // broadcast LDS.64
        #pragma unroll
        for (int m = 0; m < M; m++) {
            const float2 nxt = sx2[beta[m] + h + 1]; // stride-1 lanes, no conflict
            a0[m] += fabsf(cur[m].x - w.x);
            a1[m] += fabsf(cur[m].y - w.x);
            a0[m] += fabsf(cur[m].y - w.y);
            a1[m] += fabsf(nxt.x    - w.y);
            cur[m] = nxt;
        }
    }
    if (L & 1) {                                    // final step l = L-1
        const float w = swg[L - 1];
        #pragma unroll
        for (int m = 0; m < M; m++) {
            a0[m] += fabsf(cur[m].x - w);
            a1[m] += fabsf(cur[m].y - w);
        }
    }

    float mn = CUDART_INF_F;
    #pragma unroll
    for (int m = 0; m < M; m++) mn = fminf(mn, fminf(a0[m], a1[m]));
    #pragma unroll
    for (int o = 16; o > 0; o >>= 1)
        mn = fminf(mn, __shfl_xor_sync(0xffffffffu, mn, o));
    if (ll == 0) atomicMin(sminp, __float_as_uint(mn));   // d>=0: bits monotone
}

// sw row offsets (even): g0@0(34) g1@36(68) g2@104(101) g3@208(168)
#define SW_TOT 376

__constant__ float c_invL[4] = { 1.f/34.f, 1.f/68.f, 1.f/101.f, 1.f/168.f };

// ---------------------------------------------------------------------------
// Single launch. grid.x = 1120 workers + 21 head blocks, 256 threads (8 warps).
// Worker block = one (bc, nn); 17 passes split into 8 warp work items:
//   wk0: g0 p0-2   wk1: g0 p3-4   wk2: g1 p0-2   wk3: g1 p3-4
//   wk4: g2 p0-1   wk5: g2 p2-3   wk6: g3 p0-1   wk7: g3 p2
// Item-to-warp rotated by bid so heavy items spread across SMSPs/blocks.
// ---------------------------------------------------------------------------
__global__ __launch_bounds__(256, 6) void fused_kernel(
        const float* __restrict__ x,
        const float* __restrict__ w0,
        const float* __restrict__ w1,
        const float* __restrict__ w2,
        const float* __restrict__ w3,
        const float* __restrict__ Wout,
        float* __restrict__ d_out) {
    const int bid = blockIdx.x;
    const int tid = threadIdx.x;          // 256

    if (bid < NWORKBLK) {
        // ================= WORKER =================
        const int nn = bid % NSH;
        const int bc = bid / NSH;
        const int b  = bc / C;
        const int ch = bc % C;
        const int wp = tid >> 5;             // warp 0..7
        const int ll = tid & 31;

        __shared__ __align__(16) float sx[SXN];
        __shared__ __align__(16) float sw[SW_TOT];
        __shared__ float red[16];
        __shared__ unsigned smin[4];

        // ---- normalization: one pass sum + sumsq over the (b,ch) row ----
        const float* xrow = x + (size_t)b * T * C + ch;   // stride C over t
        float vals[2];
        float s = 0.f, ss = 0.f;
        #pragma unroll
        for (int i = 0; i < 2; i++) {
            int t = tid + i * 256;
            float v = (t < T) ? xrow[(size_t)t * C] : 0.f;
            vals[i] = v;
            s += v;
            ss += v * v;
        }
        #pragma unroll
        for (int o = 16; o > 0; o >>= 1) {
            s  += __shfl_xor_sync(0xffffffffu, s, o);
            ss += __shfl_xor_sync(0xffffffffu, ss, o);
        }
        if (ll == 0) { red[wp] = s; red[8 + wp] = ss; }
        if (tid < 4) smin[tid] = 0x7f800000u;   // +inf bits

        // ---- warps 0-3 load shapelet row of group wp ----
        if (wp < 4) {
            int L, goff;
            const float* wg;
            switch (wp) {
                case 0:  L = 34;  goff = 0;   wg = w0; break;
                case 1:  L = 68;  goff = 36;  wg = w1; break;
                case 2:  L = 101; goff = 104; wg = w2; break;
                default: L = 168; goff = 208; wg = w3; break;
            }
            const float* wrow = wg + (size_t)(nn * C + ch) * L;
            for (int i = ll; i < L; i += 32) sw[goff + i] = wrow[i];
        }

        __syncthreads();
        float stot = 0.f, sstot = 0.f;
        #pragma unroll
        for (int i = 0; i < 8; i++) { stot += red[i]; sstot += red[8 + i]; }
        const float mu  = stot * (1.0f / (float)T);
        const float var = (sstot - (float)T * mu * mu) * (1.0f / (float)(T - 1));
        const float inv = 1.0f / (sqrtf(fmaxf(var, 0.f)) + 1e-8f);

        #pragma unroll
        for (int i = 0; i < 2; i++) {
            int t = tid + i * 256;
            if (t < T) sx[t] = (vals[i] - mu) * inv;
        }
        if (tid < SXN - T) sx[T + tid] = 0.f;   // zero pad (only +inf pairs read)
        __syncthreads();

        // ---- 8 warp work items, rotated across blocks ----
        const int wk = (wp + bid) & 7;
        switch (wk) {
            case 0:  run_pass<34,  3>(sx, sw + 0,   ll, 0, &smin[0]); break;
            case 1:  run_pass<34,  2>(sx, sw + 0,   ll, 3, &smin[0]); break;
            case 2:  run_pass<68,  3>(sx, sw + 36,  ll, 0, &smin[1]); break;
            case 3:  run_pass<68,  2>(sx, sw + 36,  ll, 3, &smin[1]); break;
            case 4:  run_pass<101, 2>(sx, sw + 104, ll, 0, &smin[2]); break;
            case 5:  run_pass<101, 2>(sx, sw + 104, ll, 2, &smin[2]); break;
            case 6:  run_pass<168, 2>(sx, sw + 208, ll, 0, &smin[3]); break;
            default: run_pass<168, 1>(sx, sw + 208, ll, 2, &smin[3]); break;
        }
        __syncthreads();

        if (tid < 4) {                      // one thread per g writes results
            const float dmin = __uint_as_float(smin[tid]) * c_invL[tid];
            const int idx = b * NF + tid * (NSH * C) + nn * C + ch;
            d_out[OFF_DIST + idx] = dmin;
            d_out[OFF_PROB + idx] = expf(-dmin * dmin);   // EPS_GATE = 1
        }
        __syncthreads();
        if (tid == 0) {
            __threadfence();
            atomicAdd(&g_ctr, 1);           // publish this block's 4 results
        }
    } else {
        // ================= HEAD =================
        const int h = bid - NWORKBLK;    // 0..20

        if (tid == 0) {
            while (atomicAdd(&g_ctr, 0) < NWORKBLK) __nanosleep(64);
        }
        __syncthreads();
        __threadfence();                  // acquire published probs

        if (h < 20) {
            // 16 dots per block; warp wp does 2 dots
            const int wp = tid >> 5;
            const int ln = tid & 31;
            const float* probs = d_out + OFF_PROB;
            #pragma unroll
            for (int d = 0; d < 2; d++) {
                const int dot = h * 16 + wp * 2 + d;     // < 320
                const int bb = dot / OUTC;
                const int o  = dot % OUTC;
                const float* p  = probs + bb * NF;
                const float* wv = Wout + o * NF;
                float v = 0.f;
                #pragma unroll
                for (int f = ln; f < NF; f += 32) v += p[f] * wv[f];
                #pragma unroll
                for (int off = 16; off > 0; off >>= 1)
                    v += __shfl_xor_sync(0xffffffffu, v, off);
                if (ln == 0) d_out[OFF_OUT + dot] = v;
            }
        } else {
            // loss = 0.1 * mean|Wout|
            __shared__ float sred[8];
            float v = 0.f;
            #pragma unroll
            for (int i = tid; i < OUTC * NF; i += 256) v += fabsf(Wout[i]);
            #pragma unroll
            for (int off = 16; off > 0; off >>= 1)
                v += __shfl_xor_sync(0xffffffffu, v, off);
            if ((tid & 31) == 0) sred[tid >> 5] = v;
            __syncthreads();
            if (tid == 0) {
                float tot = 0.f;
                #pragma unroll
                for (int i = 0; i < 8; i++) tot += sred[i];
                d_out[OFF_LOSS] = 0.1f * tot / (float)(OUTC * NF);
            }
        }

        __syncthreads();
        if (tid == 0) {
            int v = atomicAdd(&g_ctr2, 1);
            if (v == NHEAD - 1) {
                // last head block resets counters for the next graph replay
                atomicExch(&g_ctr, 0);
                atomicExch(&g_ctr2, 0);
            }
        }
    }
}

// ---------------------------------------------------------------------------
extern "C" void kernel_launch(void* const* d_in, const int* in_sizes, int n_in,
                              void* d_out, int out_size) {
    const float* x    = (const float*)d_in[0];
    const float* w0   = (const float*)d_in[1];
    const float* w1   = (const float*)d_in[2];
    const float* w2   = (const float*)d_in[3];
    const float* w3   = (const float*)d_in[4];
    const float* Wout = (const float*)d_in[5];
    float* out = (float*)d_out;

    fused_kernel<<<NWORKBLK + NHEAD, 256>>>(x, w0, w1, w2, w3, Wout, out);
}